// round 6
// baseline (speedup 1.0000x reference)
#include <cuda_runtime.h>
#include <math.h>
#include <stdint.h>

// Problem constants
#define BB    64
#define TT    128
#define INW   128
#define HHD   512
#define NND   2048
#define WWD   64
#define OUTW  128
#define RRD   4
#define CTRL  384            // IN + R*W
#define KGATE 896            // CTRL + H  (14 tiles of 64)
#define JGATE 2048           // 4*H
#define JOK   448            // OUT + (R+1)*W
#define EPSF  1e-8f

// ------------------------- persistent device state -------------------------
__device__ float g_h[2][BB * HHD];             // ping-pong hidden state
__device__ float g_c[BB * HHD];
__device__ float g_M[BB * NND * WWD];          // 33.5 MB
__device__ float g_usage[BB * NND];
__device__ float g_rw[2][BB * RRD * NND];      // ping-pong read weights
__device__ float g_read_vec[BB * RRD * WWD];
__device__ float g_okbuf[BB * JOK];            // out+keys GEMM result (plain stores)
__device__ float g_wkey[BB * WWD];             // write key
__device__ int   g_lu[BB];                     // argmin(usage) per batch

// ------------------------------- reset -------------------------------------
__global__ void k_reset() {
    long idx = (long)blockIdx.x * blockDim.x + threadIdx.x;
    if (idx < (long)BB * NND * WWD) g_M[idx] = 1e-6f;
    if (idx < BB * HHD) { g_h[0][idx] = 0.f; g_h[1][idx] = 0.f; g_c[idx] = 0.f; }
    if (idx < BB * NND) g_usage[idx] = 0.f;
    if (idx < BB * RRD * NND) { g_rw[0][idx] = 0.f; g_rw[1][idx] = 0.f; }
    if (idx < BB * RRD * WWD) g_read_vec[idx] = 0.f;
    if (idx < BB) g_lu[idx] = 0;
}

__device__ __forceinline__ float sigm(float x) { return 1.f / (1.f + expf(-x)); }

// ==================== K1: gates GEMM + LSTM epilogue ========================
// grid 128 blocks x 256 threads. Block bid owns hh0 = bid*4: the 4 hidden
// units hh0..hh0+3 across ALL 4 gates (16 j values), all 64 batches, full K.
// jj = g*4 + d  ->  j = hh0 + d + g*512.
// Reads h[sel] (old), writes h[sel^1] (new) + c in place (owned elements).
__global__ void __launch_bounds__(256) k_gates(
    const float* __restrict__ xt,
    const float* __restrict__ Wih, const float* __restrict__ Whh,
    const float* __restrict__ bih, const float* __restrict__ bhh,
    int sel)
{
    __shared__ __align__(16) float4 xs4[BB * 16];   // 64 b x 64 k = 16 KB
    __shared__ __align__(16) float4 ws4[16 * 17];   // 16 j x 64 k padded
    __shared__ float sacc[16][BB];                  // acc staging, 4 KB

    const int tid = threadIdx.x;
    const int hq  = tid & 15;       // jj
    const int bq  = tid >> 4;       // 16 batch quads
    const int hh0 = blockIdx.x * 4;
    const float* __restrict__ hr = g_h[sel];

    // precompute this thread's W row index
    const int jj = hq;
    const int j  = hh0 + (jj & 3) + (jj >> 2) * 512;

    float acc[4] = {0.f, 0.f, 0.f, 0.f};

    for (int tl = 0; tl < 14; ++tl) {
        const int k0 = tl * 64;
        // stage X tile (64 b x 64 k): X = [x_t | read_vec | h_old]
#pragma unroll
        for (int li = 0; li < 4; ++li) {
            int fid = tid + 256 * li;
            int b = fid >> 4, kk4 = fid & 15;
            int k = k0 + kk4 * 4;
            const float* src;
            if (k < INW)       src = xt + b * INW + k;
            else if (k < CTRL) src = g_read_vec + b * (RRD * WWD) + (k - INW);
            else               src = hr + b * HHD + (k - CTRL);
            xs4[fid] = *reinterpret_cast<const float4*>(src);
        }
        // stage W tile (16 j x 64 k): exactly 256 float4
        {
            int r = tid >> 4, kk4 = tid & 15;
            int k = k0 + kk4 * 4;
            int jr = hh0 + (r & 3) + (r >> 2) * 512;
            const float* src = (k < CTRL) ? (Wih + (size_t)jr * CTRL + k)
                                          : (Whh + (size_t)jr * HHD + (k - CTRL));
            ws4[r * 17 + kk4] = *reinterpret_cast<const float4*>(src);
        }
        __syncthreads();
#pragma unroll
        for (int kk = 0; kk < 16; ++kk) {
            float4 wv = ws4[hq * 17 + kk];
#pragma unroll
            for (int i = 0; i < 4; ++i) {
                float4 xv = xs4[(bq * 4 + i) * 16 + kk];
                acc[i] += xv.x * wv.x + xv.y * wv.y + xv.z * wv.z + xv.w * wv.w;
            }
        }
        __syncthreads();
    }

    // stage accumulators: sacc[jj][b]
#pragma unroll
    for (int i = 0; i < 4; ++i) sacc[hq][bq * 4 + i] = acc[i];
    __syncthreads();

    // LSTM pointwise: thread t -> b = t&63, dd = t>>6 (0..3), hh = hh0+dd
    {
        const int b  = tid & 63;
        const int dd = tid >> 6;
        const int hh = hh0 + dd;
        float gi = sacc[0 * 4 + dd][b] + bih[hh]           + bhh[hh];
        float gf = sacc[1 * 4 + dd][b] + bih[512 + hh]     + bhh[512 + hh];
        float gg = sacc[2 * 4 + dd][b] + bih[1024 + hh]    + bhh[1024 + hh];
        float go = sacc[3 * 4 + dd][b] + bih[1536 + hh]    + bhh[1536 + hh];
        float c  = g_c[b * HHD + hh];
        float cn = sigm(gf) * c + sigm(gi) * tanhf(gg);
        float hn = sigm(go) * tanhf(cn);
        g_c[b * HHD + hh] = cn;
        g_h[sel ^ 1][b * HHD + hh] = hn;
    }
}

// ==================== K2: out+keys GEMM (no k-split) ========================
// grid 56 blocks x 256 threads: block owns 8 j x 64 b, full K=512.
__global__ void __launch_bounds__(256) k_ok(
    const float* __restrict__ Wout, const float* __restrict__ Wkey, int sel)
{
    __shared__ __align__(16) float4 xs4[BB * 16];
    __shared__ __align__(16) float4 ws4[8 * 17];

    const int tid = threadIdx.x;
    const int jq  = tid & 7;
    const int bq  = tid >> 3;      // 32 batch pairs
    const int j0  = blockIdx.x * 8;
    const float* __restrict__ hn = g_h[sel ^ 1];

    float acc[2] = {0.f, 0.f};

    for (int tl = 0; tl < 8; ++tl) {
        const int k0 = tl * 64;
#pragma unroll
        for (int li = 0; li < 4; ++li) {
            int fid = tid + 256 * li;
            int b = fid >> 4, kk4 = fid & 15;
            xs4[fid] = *reinterpret_cast<const float4*>(hn + b * HHD + k0 + kk4 * 4);
        }
        if (tid < 128) {
            int r = tid >> 4, kk4 = tid & 15;
            int jr = j0 + r, k = k0 + kk4 * 4;
            const float* src = (jr < OUTW) ? (Wout + (size_t)jr * HHD + k)
                                           : (Wkey + (size_t)(jr - OUTW) * HHD + k);
            ws4[r * 17 + kk4] = *reinterpret_cast<const float4*>(src);
        }
        __syncthreads();
#pragma unroll
        for (int kk = 0; kk < 16; ++kk) {
            float4 wv = ws4[jq * 17 + kk];
#pragma unroll
            for (int i = 0; i < 2; ++i) {
                float4 xv = xs4[(bq * 2 + i) * 16 + kk];
                acc[i] += xv.x * wv.x + xv.y * wv.y + xv.z * wv.z + xv.w * wv.w;
            }
        }
        __syncthreads();
    }
#pragma unroll
    for (int i = 0; i < 2; ++i)
        g_okbuf[(size_t)(bq * 2 + i) * JOK + j0 + jq] = acc[i];
}

// ============ K3: finish + sim + softmax (one block per batch) ==============
// 64 blocks x 512 threads. sim kept entirely in shared memory.
__global__ void __launch_bounds__(512) k_addr(
    const float* __restrict__ bout, const float* __restrict__ bkey,
    float* __restrict__ out, int t, int sel)
{
    __shared__ float s_sim[RRD][NND];        // 32 KB
    __shared__ float s_key[(RRD + 1) * WWD]; // 320 floats
    __shared__ __align__(16) float s_kn[RRD * WWD];
    __shared__ float s_red[512];
    __shared__ int   s_idx[512];

    const int b   = blockIdx.x;
    const int tid = threadIdx.x;
    const int wid = tid >> 5, lane = tid & 31;

    // out row
    if (tid < OUTW)
        out[(size_t)t * BB * OUTW + (size_t)b * OUTW + tid] =
            g_okbuf[(size_t)b * JOK + tid] + bout[tid];
    // keys into smem
    if (tid < (RRD + 1) * WWD)
        s_key[tid] = g_okbuf[(size_t)b * JOK + OUTW + tid] + bkey[tid];
    __syncthreads();

    // normalize the 4 read keys (warps 0-3), export write key
    if (wid < 4) {
        float v0 = s_key[wid * 64 + lane];
        float v1 = s_key[wid * 64 + lane + 32];
        float ss = v0 * v0 + v1 * v1;
#pragma unroll
        for (int o = 16; o; o >>= 1) ss += __shfl_xor_sync(0xffffffffu, ss, o);
        float inv = 1.f / (sqrtf(ss) + EPSF);
        s_kn[wid * 64 + lane]      = v0 * inv;
        s_kn[wid * 64 + lane + 32] = v1 * inv;
    }
    if (tid < WWD) g_wkey[b * WWD + tid] = s_key[RRD * WWD + tid];

    // argmin over usage[b][:], first-index tie rule
    {
        float bv = 3.4e38f; int bi = 0;
        for (int i = tid; i < NND; i += 512) {
            float u = g_usage[b * NND + i];
            if (u < bv) { bv = u; bi = i; }
        }
        s_red[tid] = bv; s_idx[tid] = bi;
        __syncthreads();
        for (int s = 256; s; s >>= 1) {
            if (tid < s) {
                float ov = s_red[tid + s]; int oi = s_idx[tid + s];
                if (ov < s_red[tid] || (ov == s_red[tid] && oi < s_idx[tid])) {
                    s_red[tid] = ov; s_idx[tid] = oi;
                }
            }
            __syncthreads();
        }
        if (tid == 0) g_lu[b] = s_idx[0];
    }
    // (s_kn visible: syncthreads above)

    // sim into shared memory: 16 warps, each handles 128 rows
    {
        const float2 k0 = ((const float2*)s_kn)[0 * 32 + lane];
        const float2 k1 = ((const float2*)s_kn)[1 * 32 + lane];
        const float2 k2 = ((const float2*)s_kn)[2 * 32 + lane];
        const float2 k3 = ((const float2*)s_kn)[3 * 32 + lane];
#pragma unroll 4
        for (int i = 0; i < 128; ++i) {
            int n = i * 16 + wid;
            float2 m = ((const float2*)(g_M + (size_t)(b * NND + n) * WWD))[lane];
            float ss = m.x * m.x + m.y * m.y;
            float d0 = m.x * k0.x + m.y * k0.y;
            float d1 = m.x * k1.x + m.y * k1.y;
            float d2 = m.x * k2.x + m.y * k2.y;
            float d3 = m.x * k3.x + m.y * k3.y;
#pragma unroll
            for (int o = 16; o; o >>= 1) {
                ss += __shfl_xor_sync(0xffffffffu, ss, o);
                d0 += __shfl_xor_sync(0xffffffffu, d0, o);
                d1 += __shfl_xor_sync(0xffffffffu, d1, o);
                d2 += __shfl_xor_sync(0xffffffffu, d2, o);
                d3 += __shfl_xor_sync(0xffffffffu, d3, o);
            }
            if (lane == 0) {
                float inv = 1.f / (sqrtf(ss) + EPSF);
                s_sim[0][n] = d0 * inv;
                s_sim[1][n] = d1 * inv;
                s_sim[2][n] = d2 * inv;
                s_sim[3][n] = d3 * inv;
            }
        }
    }
    __syncthreads();

    // softmax per r: 128-thread group per r, 16 elems/thread
    {
        const int r = tid >> 7;        // 0..3
        const int c = tid & 127;
        float v[16];
        float m = -3.4e38f;
#pragma unroll
        for (int j = 0; j < 16; ++j) { v[j] = s_sim[r][c + 128 * j]; m = fmaxf(m, v[j]); }
        s_red[tid] = m; __syncthreads();
        for (int st = 64; st; st >>= 1) {
            if (c < st) s_red[tid] = fmaxf(s_red[tid], s_red[tid + st]);
            __syncthreads();
        }
        m = s_red[r << 7];
        __syncthreads();
        float sum = 0.f;
#pragma unroll
        for (int j = 0; j < 16; ++j) { v[j] = expf(v[j] - m); sum += v[j]; }
        s_red[tid] = sum; __syncthreads();
        for (int st = 64; st; st >>= 1) {
            if (c < st) s_red[tid] += s_red[tid + st];
            __syncthreads();
        }
        float inv = 1.f / s_red[r << 7];
        float* rw_new = g_rw[sel] + (size_t)(b * RRD + r) * NND;
#pragma unroll
        for (int j = 0; j < 16; ++j)
            rw_new[c + 128 * j] = v[j] * inv;
    }

    // zero read_vec for K4's atomic accumulation
    if (tid < RRD * WWD) g_read_vec[b * RRD * WWD + tid] = 0.f;
}

// ==================== K4: memory update =====================================
// single pass over M: read_vec (old M), write M_new, update usage.
__global__ void __launch_bounds__(256) k_update(int sel,
                                                const float* __restrict__ alpha,
                                                const float* __restrict__ gamma) {
    const int b   = blockIdx.y;
    const int cx  = blockIdx.x;       // 16 chunks x 128 n
    const int tid = threadIdx.x, wid = tid >> 5, lane = tid & 31;
    const float* __restrict__ rw_new = g_rw[sel];
    const float* __restrict__ rw_old = g_rw[sel ^ 1];
    const float sa = 1.f / (1.f + expf(-alpha[0]));
    const float gm = gamma[0];
    const int lu = g_lu[b];

    __shared__ __align__(16) float wk[WWD];
    if (tid < WWD) wk[tid] = g_wkey[b * WWD + tid];
    __syncthreads();
    const float2 wk2 = ((const float2*)wk)[lane];

    float2 a0 = {0.f, 0.f}, a1 = {0.f, 0.f}, a2 = {0.f, 0.f}, a3 = {0.f, 0.f};
#pragma unroll 4
    for (int i = 0; i < 16; ++i) {
        int n = cx * 128 + wid * 16 + i;
        size_t moff = (size_t)(b * NND + n) * WWD;
        float2 m = ((const float2*)(g_M + moff))[lane];
        float r0o = rw_old[(size_t)(b * RRD + 0) * NND + n];
        float r1o = rw_old[(size_t)(b * RRD + 1) * NND + n];
        float r2o = rw_old[(size_t)(b * RRD + 2) * NND + n];
        float r3o = rw_old[(size_t)(b * RRD + 3) * NND + n];
        float r0 = rw_new[(size_t)(b * RRD + 0) * NND + n];
        float r1 = rw_new[(size_t)(b * RRD + 1) * NND + n];
        float r2 = rw_new[(size_t)(b * RRD + 2) * NND + n];
        float r3 = rw_new[(size_t)(b * RRD + 3) * NND + n];
        float so = r0o + r1o + r2o + r3o;
        bool is_lu = (n == lu);
        float ww = sa * so + (is_lu ? (1.f - sa) : 0.f);
        float2 mn;
        mn.x = (is_lu ? 0.f : m.x) + ww * wk2.x;
        mn.y = (is_lu ? 0.f : m.y) + ww * wk2.y;
        ((float2*)(g_M + moff))[lane] = mn;
        // read_vec uses OLD M
        a0.x += r0 * m.x; a0.y += r0 * m.y;
        a1.x += r1 * m.x; a1.y += r1 * m.y;
        a2.x += r2 * m.x; a2.y += r2 * m.y;
        a3.x += r3 * m.x; a3.y += r3 * m.y;
        if (lane == 0)
            g_usage[b * NND + n] = gm * g_usage[b * NND + n] + (r0 + r1 + r2 + r3) + ww;
    }
    // cross-warp reduce into read_vec
    __shared__ float red[8][RRD * WWD];
    float* rp = red[wid];
    rp[0 * WWD + 2 * lane] = a0.x; rp[0 * WWD + 2 * lane + 1] = a0.y;
    rp[1 * WWD + 2 * lane] = a1.x; rp[1 * WWD + 2 * lane + 1] = a1.y;
    rp[2 * WWD + 2 * lane] = a2.x; rp[2 * WWD + 2 * lane + 1] = a2.y;
    rp[3 * WWD + 2 * lane] = a3.x; rp[3 * WWD + 2 * lane + 1] = a3.y;
    __syncthreads();
    if (tid < RRD * WWD) {
        float s = 0.f;
#pragma unroll
        for (int w = 0; w < 8; ++w) s += red[w][tid];
        atomicAdd(&g_read_vec[b * RRD * WWD + tid], s);
    }
}

// ------------------------------- launcher ------------------------------------
extern "C" void kernel_launch(void* const* d_in, const int* in_sizes, int n_in,
                              void* d_out, int out_size) {
    const float* x_seq = (const float*)d_in[0];
    const float* Wih   = (const float*)d_in[1];
    const float* Whh   = (const float*)d_in[2];
    const float* bih   = (const float*)d_in[3];
    const float* bhh   = (const float*)d_in[4];
    const float* Wout  = (const float*)d_in[5];
    const float* bout  = (const float*)d_in[6];
    const float* Wkey  = (const float*)d_in[7];
    const float* bkey  = (const float*)d_in[8];
    const float* alpha = (const float*)d_in[9];
    const float* gamma = (const float*)d_in[10];
    float* out = (float*)d_out;

    k_reset<<<32768, 256>>>();

    for (int t = 0; t < TT; ++t) {
        const int sel = t & 1;
        k_gates<<<JGATE / 16, 256>>>(x_seq + (size_t)t * BB * INW,
                                     Wih, Whh, bih, bhh, sel);
        k_ok<<<JOK / 8, 256>>>(Wout, Wkey, sel);
        k_addr<<<BB, 512>>>(bout, bkey, out, t, sel);
        k_update<<<dim3(16, BB), 256>>>(sel, alpha, gamma);
    }
}

// round 7
// speedup vs baseline: 1.8232x; 1.8232x over previous
#include <cuda_runtime.h>
#include <math.h>
#include <stdint.h>

// Problem constants
#define BB    64
#define TT    128
#define INW   128
#define HHD   512
#define NND   2048
#define WWD   64
#define OUTW  128
#define RRD   4
#define CTRL  384            // IN + R*W
#define KGATE 896            // CTRL + H  (14 tiles of 64)
#define JGATE 2048           // 4*H
#define JOK   448            // OUT + (R+1)*W
#define EPSF  1e-8f

// ------------------------- persistent device state -------------------------
__device__ float g_h[2][BB * HHD];             // ping-pong hidden state
__device__ float g_c[BB * HHD];
__device__ float g_M[BB * NND * WWD];          // 33.5 MB
__device__ float g_usage[BB * NND];
__device__ float g_rw[2][BB * RRD * NND];      // ping-pong read weights
__device__ float g_read_vec[BB * RRD * WWD];
__device__ float g_sim[BB * RRD * NND];
__device__ float g_Kn[BB * RRD * WWD];         // normalized read keys
__device__ float g_wkey[BB * WWD];             // write key
__device__ int   g_lu[BB];                     // argmin(usage) per batch

// ------------------------------- reset -------------------------------------
__global__ void k_reset() {
    long idx = (long)blockIdx.x * blockDim.x + threadIdx.x;
    if (idx < (long)BB * NND * WWD) g_M[idx] = 1e-6f;
    if (idx < BB * HHD) { g_h[0][idx] = 0.f; g_h[1][idx] = 0.f; g_c[idx] = 0.f; }
    if (idx < BB * NND) g_usage[idx] = 0.f;
    if (idx < BB * RRD * NND) { g_rw[0][idx] = 0.f; g_rw[1][idx] = 0.f; }
    if (idx < BB * RRD * WWD) g_read_vec[idx] = 0.f;
    if (idx < BB) g_lu[idx] = 0;
}

__device__ __forceinline__ float sigm(float x) { return 1.f / (1.f + expf(-x)); }

// ==================== K1: gates GEMM + LSTM epilogue ========================
// grid 128 blocks x 256 threads. Block bid owns hh0 = bid*4: the 4 hidden
// units hh0..hh0+3 across ALL 4 gates (16 j values), all 64 batches, full K.
// Register double-buffering: tile t+1 loads overlap tile t compute.
__global__ void __launch_bounds__(256) k_gates(
    const float* __restrict__ xt,
    const float* __restrict__ Wih, const float* __restrict__ Whh,
    const float* __restrict__ bih, const float* __restrict__ bhh,
    int sel)
{
    __shared__ __align__(16) float4 xs4[BB * 16];   // 64 b x 64 k = 16 KB
    __shared__ __align__(16) float4 ws4[16 * 17];   // 16 j x 64 k padded
    __shared__ float sacc[16][BB];                  // acc staging, 4 KB

    const int tid = threadIdx.x;
    const int hq  = tid & 15;       // jj
    const int bq  = tid >> 4;       // 16 batch quads
    const int hh0 = blockIdx.x * 4;
    const float* __restrict__ hr = g_h[sel];

    // this thread's staging indices
    const int xb   = tid >> 4;          // batch row for x staging
    const int xk4  = tid & 15;
    const int wr_r = tid >> 4;          // W row (16 rows)
    const int jr   = hh0 + (wr_r & 3) + (wr_r >> 2) * 512;

    float acc[4] = {0.f, 0.f, 0.f, 0.f};

    float4 xreg[4];
    float4 wreg;

    // prologue: load tile 0 into registers
    {
        const int k0 = 0;
#pragma unroll
        for (int li = 0; li < 4; ++li) {
            int b = xb + 16 * li * 1;   // fid = tid + 256*li -> b = (tid+256li)>>4 = xb + 16li
            int k = k0 + xk4 * 4;
            const float* src;
            if (k < INW)       src = xt + b * INW + k;
            else if (k < CTRL) src = g_read_vec + b * (RRD * WWD) + (k - INW);
            else               src = hr + b * HHD + (k - CTRL);
            xreg[li] = *reinterpret_cast<const float4*>(src);
        }
        int k = k0 + xk4 * 4;
        const float* src = (k < CTRL) ? (Wih + (size_t)jr * CTRL + k)
                                      : (Whh + (size_t)jr * HHD + (k - CTRL));
        wreg = *reinterpret_cast<const float4*>(src);
    }

    for (int tl = 0; tl < 14; ++tl) {
        // commit staged registers to smem
#pragma unroll
        for (int li = 0; li < 4; ++li)
            xs4[(xb + 16 * li) * 16 + xk4] = xreg[li];
        ws4[wr_r * 17 + xk4] = wreg;
        __syncthreads();

        // prefetch next tile
        if (tl + 1 < 14) {
            const int k0 = (tl + 1) * 64;
#pragma unroll
            for (int li = 0; li < 4; ++li) {
                int b = xb + 16 * li;
                int k = k0 + xk4 * 4;
                const float* src;
                if (k < INW)       src = xt + b * INW + k;
                else if (k < CTRL) src = g_read_vec + b * (RRD * WWD) + (k - INW);
                else               src = hr + b * HHD + (k - CTRL);
                xreg[li] = *reinterpret_cast<const float4*>(src);
            }
            int k = k0 + xk4 * 4;
            const float* src = (k < CTRL) ? (Wih + (size_t)jr * CTRL + k)
                                          : (Whh + (size_t)jr * HHD + (k - CTRL));
            wreg = *reinterpret_cast<const float4*>(src);
        }

        // compute current tile
#pragma unroll
        for (int kk = 0; kk < 16; ++kk) {
            float4 wv = ws4[hq * 17 + kk];
#pragma unroll
            for (int i = 0; i < 4; ++i) {
                float4 xv = xs4[(bq * 4 + i) * 16 + kk];
                acc[i] += xv.x * wv.x + xv.y * wv.y + xv.z * wv.z + xv.w * wv.w;
            }
        }
        __syncthreads();
    }

    // stage accumulators: sacc[jj][b]
#pragma unroll
    for (int i = 0; i < 4; ++i) sacc[hq][bq * 4 + i] = acc[i];
    __syncthreads();

    // LSTM pointwise: thread t -> b = t&63, dd = t>>6 (0..3), hh = hh0+dd
    {
        const int b  = tid & 63;
        const int dd = tid >> 6;
        const int hh = hh0 + dd;
        float gi = sacc[0 * 4 + dd][b] + bih[hh]           + bhh[hh];
        float gf = sacc[1 * 4 + dd][b] + bih[512 + hh]     + bhh[512 + hh];
        float gg = sacc[2 * 4 + dd][b] + bih[1024 + hh]    + bhh[1024 + hh];
        float go = sacc[3 * 4 + dd][b] + bih[1536 + hh]    + bhh[1536 + hh];
        float c  = g_c[b * HHD + hh];
        float cn = sigm(gf) * c + sigm(gi) * tanhf(gg);
        float hn = sigm(go) * tanhf(cn);
        g_c[b * HHD + hh] = cn;
        g_h[sel ^ 1][b * HHD + hh] = hn;
    }
}

// ========== K2: out+keys GEMM with fused finish epilogue ====================
// grid (7 j-groups, 32 batch-pairs) x 256 threads. Block (jg, bp) computes
// y[bb][jj] = h[b0+bb] . W[jg*64+jj] for jj in [0,64), bb in {0,1}, then:
//   jg 0,1  -> out rows (bias bout)
//   jg 2..5 -> read key r=jg-2: add bkey, L2-normalize, write g_Kn
//   jg 6    -> write key: add bkey, write g_wkey
__global__ void __launch_bounds__(256) k_ok2(
    const float* __restrict__ Wout, const float* __restrict__ Wkey,
    const float* __restrict__ bout, const float* __restrict__ bkey,
    float* __restrict__ out, int t, int sel)
{
    __shared__ __align__(16) float4 hs[2][128];   // 2 batches x 512 floats
    __shared__ float ys[2][64];
    __shared__ float sinv[2];

    const int tid  = threadIdx.x;
    const int wid  = tid >> 5, lane = tid & 31;
    const int jg   = blockIdx.x;
    const int b0   = blockIdx.y * 2;
    const int j0   = jg * 64;
    const float* __restrict__ hn = g_h[sel ^ 1];

    {
        int bb = tid >> 7, idx = tid & 127;
        hs[bb][idx] = ((const float4*)(hn + (size_t)(b0 + bb) * HHD))[idx];
    }
    __syncthreads();

    // warp wid handles 8 rows: j = j0 + wid*8 + jj
#pragma unroll 2
    for (int jj = 0; jj < 8; ++jj) {
        int j = j0 + wid * 8 + jj;
        const float* wrow = (j < OUTW) ? (Wout + (size_t)j * HHD)
                                       : (Wkey + (size_t)(j - OUTW) * HHD);
        const float4* w4 = (const float4*)wrow;
        float s0 = 0.f, s1 = 0.f;
#pragma unroll
        for (int it = 0; it < 4; ++it) {
            float4 w = w4[lane + 32 * it];
            float4 h0 = hs[0][lane + 32 * it];
            float4 h1 = hs[1][lane + 32 * it];
            s0 += w.x * h0.x + w.y * h0.y + w.z * h0.z + w.w * h0.w;
            s1 += w.x * h1.x + w.y * h1.y + w.z * h1.z + w.w * h1.w;
        }
#pragma unroll
        for (int o = 16; o; o >>= 1) {
            s0 += __shfl_xor_sync(0xffffffffu, s0, o);
            s1 += __shfl_xor_sync(0xffffffffu, s1, o);
        }
        if (lane == 0) { ys[0][wid * 8 + jj] = s0; ys[1][wid * 8 + jj] = s1; }
    }
    __syncthreads();

    // epilogue
    if (jg < 2) {
        if (tid < 128) {
            int bb = tid >> 6, jj = tid & 63;
            out[(size_t)t * BB * OUTW + (size_t)(b0 + bb) * OUTW + j0 + jj] =
                ys[bb][jj] + bout[j0 + jj];
        }
    } else if (jg == 6) {
        if (tid < 128) {
            int bb = tid >> 6, jj = tid & 63;
            g_wkey[(b0 + bb) * WWD + jj] = ys[bb][jj] + bkey[4 * 64 + jj];
        }
    } else {
        const int kb = (jg - 2) * 64;   // bkey offset; Kn offset = kb too
        if (tid < 128) {
            int bb = tid >> 6, jj = tid & 63;
            ys[bb][jj] += bkey[kb + jj];
        }
        __syncthreads();
        if (wid < 2) {
            float v0 = ys[wid][lane];
            float v1 = ys[wid][lane + 32];
            float ss = v0 * v0 + v1 * v1;
#pragma unroll
            for (int o = 16; o; o >>= 1) ss += __shfl_xor_sync(0xffffffffu, ss, o);
            if (lane == 0) sinv[wid] = 1.f / (sqrtf(ss) + EPSF);
        }
        __syncthreads();
        if (tid < 128) {
            int bb = tid >> 6, jj = tid & 63;
            g_Kn[(b0 + bb) * (RRD * WWD) + kb + jj] = ys[bb][jj] * sinv[bb];
        }
    }
}

// ==================== K3: sim ===============================================
// sim[b][r][n] = (Kn[b][r] . M[b][n]) / (||M[b][n]|| + eps)
__global__ void __launch_bounds__(256) k_sim() {
    const int b   = blockIdx.y;
    const int nb  = blockIdx.x;       // 32 blocks x 64 n
    const int tid = threadIdx.x, wid = tid >> 5, lane = tid & 31;
    __shared__ __align__(16) float kn[RRD * WWD];
    if (tid < RRD * WWD) kn[tid] = g_Kn[b * RRD * WWD + tid];
    __syncthreads();
    const float2 k0 = ((const float2*)kn)[0 * 32 + lane];
    const float2 k1 = ((const float2*)kn)[1 * 32 + lane];
    const float2 k2 = ((const float2*)kn)[2 * 32 + lane];
    const float2 k3 = ((const float2*)kn)[3 * 32 + lane];
#pragma unroll
    for (int i = 0; i < 8; ++i) {
        int n = nb * 64 + wid * 8 + i;
        float2 m = ((const float2*)(g_M + (size_t)(b * NND + n) * WWD))[lane];
        float ss = m.x * m.x + m.y * m.y;
        float d0 = m.x * k0.x + m.y * k0.y;
        float d1 = m.x * k1.x + m.y * k1.y;
        float d2 = m.x * k2.x + m.y * k2.y;
        float d3 = m.x * k3.x + m.y * k3.y;
#pragma unroll
        for (int o = 16; o; o >>= 1) {
            ss += __shfl_xor_sync(0xffffffffu, ss, o);
            d0 += __shfl_xor_sync(0xffffffffu, d0, o);
            d1 += __shfl_xor_sync(0xffffffffu, d1, o);
            d2 += __shfl_xor_sync(0xffffffffu, d2, o);
            d3 += __shfl_xor_sync(0xffffffffu, d3, o);
        }
        if (lane == 0) {
            float inv = 1.f / (sqrtf(ss) + EPSF);
            g_sim[(size_t)(b * RRD + 0) * NND + n] = d0 * inv;
            g_sim[(size_t)(b * RRD + 1) * NND + n] = d1 * inv;
            g_sim[(size_t)(b * RRD + 2) * NND + n] = d2 * inv;
            g_sim[(size_t)(b * RRD + 3) * NND + n] = d3 * inv;
        }
    }
}

// ==================== K4: softmax (+ argmin & read_vec zero on r==0) ========
__global__ void k_softmax(int sel) {
    const int br  = blockIdx.x;       // b*4 + r
    const int tid = threadIdx.x;      // 256
    float* __restrict__ rw_new = g_rw[sel];
    const float* s = g_sim + (size_t)br * NND;
    float v[8];
    float m = -3.4e38f;
#pragma unroll
    for (int j = 0; j < 8; ++j) { v[j] = s[tid + 256 * j]; m = fmaxf(m, v[j]); }
    __shared__ float red[256];
    red[tid] = m; __syncthreads();
    for (int st = 128; st; st >>= 1) { if (tid < st) red[tid] = fmaxf(red[tid], red[tid + st]); __syncthreads(); }
    m = red[0];
    __syncthreads();
    float sum = 0.f;
#pragma unroll
    for (int j = 0; j < 8; ++j) { v[j] = expf(v[j] - m); sum += v[j]; }
    red[tid] = sum; __syncthreads();
    for (int st = 128; st; st >>= 1) { if (tid < st) red[tid] += red[tid + st]; __syncthreads(); }
    float inv = 1.f / red[0];
#pragma unroll
    for (int j = 0; j < 8; ++j)
        rw_new[(size_t)br * NND + tid + 256 * j] = v[j] * inv;

    // r==0 block: argmin(usage[b]) with first-index tie rule + zero read_vec
    if ((br & 3) == 0) {
        const int b = br >> 2;
        __shared__ int si[256];
        __syncthreads();
        float bv = 3.4e38f; int bi = 0;
        for (int i = tid; i < NND; i += 256) {
            float u = g_usage[b * NND + i];
            if (u < bv) { bv = u; bi = i; }
        }
        red[tid] = bv; si[tid] = bi;
        __syncthreads();
        for (int s2 = 128; s2; s2 >>= 1) {
            if (tid < s2) {
                float ov = red[tid + s2]; int oi = si[tid + s2];
                if (ov < red[tid] || (ov == red[tid] && oi < si[tid])) { red[tid] = ov; si[tid] = oi; }
            }
            __syncthreads();
        }
        if (tid == 0) g_lu[b] = si[0];
        g_read_vec[b * RRD * WWD + tid] = 0.f;
    }
}

// ==================== K5: memory update =====================================
// single pass over M: read_vec (old M), write M_new, update usage.
__global__ void __launch_bounds__(256) k_update(int sel,
                                                const float* __restrict__ alpha,
                                                const float* __restrict__ gamma) {
    const int b   = blockIdx.y;
    const int cx  = blockIdx.x;       // 16 chunks x 128 n
    const int tid = threadIdx.x, wid = tid >> 5, lane = tid & 31;
    const float* __restrict__ rw_new = g_rw[sel];
    const float* __restrict__ rw_old = g_rw[sel ^ 1];
    const float sa = 1.f / (1.f + expf(-alpha[0]));
    const float gm = gamma[0];
    const int lu = g_lu[b];

    __shared__ __align__(16) float wk[WWD];
    if (tid < WWD) wk[tid] = g_wkey[b * WWD + tid];
    __syncthreads();
    const float2 wk2 = ((const float2*)wk)[lane];

    float2 a0 = {0.f, 0.f}, a1 = {0.f, 0.f}, a2 = {0.f, 0.f}, a3 = {0.f, 0.f};
#pragma unroll 4
    for (int i = 0; i < 16; ++i) {
        int n = cx * 128 + wid * 16 + i;
        size_t moff = (size_t)(b * NND + n) * WWD;
        float2 m = ((const float2*)(g_M + moff))[lane];
        float r0o = rw_old[(size_t)(b * RRD + 0) * NND + n];
        float r1o = rw_old[(size_t)(b * RRD + 1) * NND + n];
        float r2o = rw_old[(size_t)(b * RRD + 2) * NND + n];
        float r3o = rw_old[(size_t)(b * RRD + 3) * NND + n];
        float r0 = rw_new[(size_t)(b * RRD + 0) * NND + n];
        float r1 = rw_new[(size_t)(b * RRD + 1) * NND + n];
        float r2 = rw_new[(size_t)(b * RRD + 2) * NND + n];
        float r3 = rw_new[(size_t)(b * RRD + 3) * NND + n];
        float so = r0o + r1o + r2o + r3o;
        bool is_lu = (n == lu);
        float ww = sa * so + (is_lu ? (1.f - sa) : 0.f);
        float2 mn;
        mn.x = (is_lu ? 0.f : m.x) + ww * wk2.x;
        mn.y = (is_lu ? 0.f : m.y) + ww * wk2.y;
        ((float2*)(g_M + moff))[lane] = mn;
        // read_vec uses OLD M
        a0.x += r0 * m.x; a0.y += r0 * m.y;
        a1.x += r1 * m.x; a1.y += r1 * m.y;
        a2.x += r2 * m.x; a2.y += r2 * m.y;
        a3.x += r3 * m.x; a3.y += r3 * m.y;
        if (lane == 0)
            g_usage[b * NND + n] = gm * g_usage[b * NND + n] + (r0 + r1 + r2 + r3) + ww;
    }
    // cross-warp reduce into read_vec
    __shared__ float red[8][RRD * WWD];
    float* rp = red[wid];
    rp[0 * WWD + 2 * lane] = a0.x; rp[0 * WWD + 2 * lane + 1] = a0.y;
    rp[1 * WWD + 2 * lane] = a1.x; rp[1 * WWD + 2 * lane + 1] = a1.y;
    rp[2 * WWD + 2 * lane] = a2.x; rp[2 * WWD + 2 * lane + 1] = a2.y;
    rp[3 * WWD + 2 * lane] = a3.x; rp[3 * WWD + 2 * lane + 1] = a3.y;
    __syncthreads();
    if (tid < RRD * WWD) {
        float s = 0.f;
#pragma unroll
        for (int w = 0; w < 8; ++w) s += red[w][tid];
        atomicAdd(&g_read_vec[b * RRD * WWD + tid], s);
    }
}

// ------------------------------- launcher ------------------------------------
extern "C" void kernel_launch(void* const* d_in, const int* in_sizes, int n_in,
                              void* d_out, int out_size) {
    const float* x_seq = (const float*)d_in[0];
    const float* Wih   = (const float*)d_in[1];
    const float* Whh   = (const float*)d_in[2];
    const float* bih   = (const float*)d_in[3];
    const float* bhh   = (const float*)d_in[4];
    const float* Wout  = (const float*)d_in[5];
    const float* bout  = (const float*)d_in[6];
    const float* Wkey  = (const float*)d_in[7];
    const float* bkey  = (const float*)d_in[8];
    const float* alpha = (const float*)d_in[9];
    const float* gamma = (const float*)d_in[10];
    float* out = (float*)d_out;

    k_reset<<<32768, 256>>>();

    for (int t = 0; t < TT; ++t) {
        const int sel = t & 1;
        k_gates<<<JGATE / 16, 256>>>(x_seq + (size_t)t * BB * INW,
                                     Wih, Whh, bih, bhh, sel);
        k_ok2<<<dim3(7, 32), 256>>>(Wout, Wkey, bout, bkey, out, t, sel);
        k_sim<<<dim3(32, BB), 256>>>();
        k_softmax<<<BB * RRD, 256>>>(sel);
        k_update<<<dim3(16, BB), 256>>>(sel, alpha, gamma);
    }
}

// round 8
// speedup vs baseline: 2.2066x; 1.2103x over previous
#include <cuda_runtime.h>
#include <math.h>
#include <stdint.h>

// Problem constants
#define BB    64
#define TT    128
#define INW   128
#define HHD   512
#define NND   2048
#define WWD   64
#define OUTW  128
#define RRD   4
#define CTRL  384            // IN + R*W
#define KGATE 896            // CTRL + H  (14 tiles of 64)
#define JGATE 2048           // 4*H
#define JOK   448            // OUT + (R+1)*W
#define EPSF  1e-8f

// ------------------------- persistent device state -------------------------
__device__ float g_h[2][BB * HHD];             // ping-pong hidden state
__device__ float g_c[BB * HHD];
__device__ float g_M[BB * NND * WWD];          // 33.5 MB
__device__ float g_usage[BB * NND];
__device__ float g_rw[2][BB * RRD * NND];      // ping-pong read weights
__device__ float g_read_vec[BB * RRD * WWD];
__device__ float g_sim[BB * RRD * NND];
__device__ float g_Kn[BB * RRD * WWD];         // normalized read keys
__device__ float g_wkey[BB * WWD];             // write key
__device__ int   g_lu[BB];                     // argmin(usage) per batch

// ------------------------------- reset -------------------------------------
__global__ void k_reset() {
    long idx = (long)blockIdx.x * blockDim.x + threadIdx.x;
    if (idx < (long)BB * NND * WWD) g_M[idx] = 1e-6f;
    if (idx < BB * HHD) { g_h[0][idx] = 0.f; g_h[1][idx] = 0.f; g_c[idx] = 0.f; }
    if (idx < BB * NND) g_usage[idx] = 0.f;
    if (idx < BB * RRD * NND) { g_rw[0][idx] = 0.f; g_rw[1][idx] = 0.f; }
    if (idx < BB * RRD * WWD) g_read_vec[idx] = 0.f;
    if (idx < BB) g_lu[idx] = 0;
}

__device__ __forceinline__ float sigm(float x) { return 1.f / (1.f + expf(-x)); }

// ==================== K1: gates GEMM + LSTM epilogue ========================
// grid 128 blocks x 256 threads. Block bid owns hh0 = bid*4: the 4 hidden
// units hh0..hh0+3 across ALL 4 gates (16 j values), all 64 batches, full K.
// Register double-buffering: tile t+1 loads overlap tile t compute.
__global__ void __launch_bounds__(256) k_gates(
    const float* __restrict__ xt,
    const float* __restrict__ Wih, const float* __restrict__ Whh,
    const float* __restrict__ bih, const float* __restrict__ bhh,
    int sel)
{
    __shared__ __align__(16) float4 xs4[BB * 16];   // 64 b x 64 k = 16 KB
    __shared__ __align__(16) float4 ws4[16 * 17];   // 16 j x 64 k padded
    __shared__ float sacc[16][BB];                  // acc staging, 4 KB

    const int tid = threadIdx.x;
    const int hq  = tid & 15;       // jj
    const int bq  = tid >> 4;       // 16 batch quads
    const int hh0 = blockIdx.x * 4;
    const float* __restrict__ hr = g_h[sel];

    // this thread's staging indices
    const int xb   = tid >> 4;          // batch row for x staging
    const int xk4  = tid & 15;
    const int wr_r = tid >> 4;          // W row (16 rows)
    const int jr   = hh0 + (wr_r & 3) + (wr_r >> 2) * 512;

    float acc[4] = {0.f, 0.f, 0.f, 0.f};

    float4 xreg[4];
    float4 wreg;

    // prologue: load tile 0 into registers
    {
        const int k0 = 0;
#pragma unroll
        for (int li = 0; li < 4; ++li) {
            int b = xb + 16 * li;
            int k = k0 + xk4 * 4;
            const float* src;
            if (k < INW)       src = xt + b * INW + k;
            else if (k < CTRL) src = g_read_vec + b * (RRD * WWD) + (k - INW);
            else               src = hr + b * HHD + (k - CTRL);
            xreg[li] = *reinterpret_cast<const float4*>(src);
        }
        int k = k0 + xk4 * 4;
        const float* src = (k < CTRL) ? (Wih + (size_t)jr * CTRL + k)
                                      : (Whh + (size_t)jr * HHD + (k - CTRL));
        wreg = *reinterpret_cast<const float4*>(src);
    }

    for (int tl = 0; tl < 14; ++tl) {
        // commit staged registers to smem
#pragma unroll
        for (int li = 0; li < 4; ++li)
            xs4[(xb + 16 * li) * 16 + xk4] = xreg[li];
        ws4[wr_r * 17 + xk4] = wreg;
        __syncthreads();

        // prefetch next tile
        if (tl + 1 < 14) {
            const int k0 = (tl + 1) * 64;
#pragma unroll
            for (int li = 0; li < 4; ++li) {
                int b = xb + 16 * li;
                int k = k0 + xk4 * 4;
                const float* src;
                if (k < INW)       src = xt + b * INW + k;
                else if (k < CTRL) src = g_read_vec + b * (RRD * WWD) + (k - INW);
                else               src = hr + b * HHD + (k - CTRL);
                xreg[li] = *reinterpret_cast<const float4*>(src);
            }
            int k = k0 + xk4 * 4;
            const float* src = (k < CTRL) ? (Wih + (size_t)jr * CTRL + k)
                                          : (Whh + (size_t)jr * HHD + (k - CTRL));
            wreg = *reinterpret_cast<const float4*>(src);
        }

        // compute current tile
#pragma unroll
        for (int kk = 0; kk < 16; ++kk) {
            float4 wv = ws4[hq * 17 + kk];
#pragma unroll
            for (int i = 0; i < 4; ++i) {
                float4 xv = xs4[(bq * 4 + i) * 16 + kk];
                acc[i] += xv.x * wv.x + xv.y * wv.y + xv.z * wv.z + xv.w * wv.w;
            }
        }
        __syncthreads();
    }

    // stage accumulators: sacc[jj][b]
#pragma unroll
    for (int i = 0; i < 4; ++i) sacc[hq][bq * 4 + i] = acc[i];
    __syncthreads();

    // LSTM pointwise: thread t -> b = t&63, dd = t>>6 (0..3), hh = hh0+dd
    {
        const int b  = tid & 63;
        const int dd = tid >> 6;
        const int hh = hh0 + dd;
        float gi = sacc[0 * 4 + dd][b] + bih[hh]           + bhh[hh];
        float gf = sacc[1 * 4 + dd][b] + bih[512 + hh]     + bhh[512 + hh];
        float gg = sacc[2 * 4 + dd][b] + bih[1024 + hh]    + bhh[1024 + hh];
        float go = sacc[3 * 4 + dd][b] + bih[1536 + hh]    + bhh[1536 + hh];
        float c  = g_c[b * HHD + hh];
        float cn = sigm(gf) * c + sigm(gi) * tanhf(gg);
        float hn = sigm(go) * tanhf(cn);
        g_c[b * HHD + hh] = cn;
        g_h[sel ^ 1][b * HHD + hh] = hn;
    }
}

// ========== K2: out+keys GEMM with fused finish epilogue ====================
// grid (7 j-groups, 32 batch-pairs) x 256 threads. Block (jg, bp) computes
// y[bb][jj] = h[b0+bb] . W[jg*64+jj] for jj in [0,64), bb in {0,1}, then:
//   jg 0,1  -> out rows (bias bout)
//   jg 2..5 -> read key r=jg-2: add bkey, L2-normalize, write g_Kn
//   jg 6    -> write key: add bkey, write g_wkey
__global__ void __launch_bounds__(256) k_ok2(
    const float* __restrict__ Wout, const float* __restrict__ Wkey,
    const float* __restrict__ bout, const float* __restrict__ bkey,
    float* __restrict__ out, int t, int sel)
{
    __shared__ __align__(16) float4 hs[2][128];   // 2 batches x 512 floats
    __shared__ float ys[2][64];
    __shared__ float sinv[2];

    const int tid  = threadIdx.x;
    const int wid  = tid >> 5, lane = tid & 31;
    const int jg   = blockIdx.x;
    const int b0   = blockIdx.y * 2;
    const int j0   = jg * 64;
    const float* __restrict__ hn = g_h[sel ^ 1];

    {
        int bb = tid >> 7, idx = tid & 127;
        hs[bb][idx] = ((const float4*)(hn + (size_t)(b0 + bb) * HHD))[idx];
    }
    __syncthreads();

    // warp wid handles 8 rows: j = j0 + wid*8 + jj
#pragma unroll 2
    for (int jj = 0; jj < 8; ++jj) {
        int j = j0 + wid * 8 + jj;
        const float* wrow = (j < OUTW) ? (Wout + (size_t)j * HHD)
                                       : (Wkey + (size_t)(j - OUTW) * HHD);
        const float4* w4 = (const float4*)wrow;
        float s0 = 0.f, s1 = 0.f;
#pragma unroll
        for (int it = 0; it < 4; ++it) {
            float4 w = w4[lane + 32 * it];
            float4 h0 = hs[0][lane + 32 * it];
            float4 h1 = hs[1][lane + 32 * it];
            s0 += w.x * h0.x + w.y * h0.y + w.z * h0.z + w.w * h0.w;
            s1 += w.x * h1.x + w.y * h1.y + w.z * h1.z + w.w * h1.w;
        }
#pragma unroll
        for (int o = 16; o; o >>= 1) {
            s0 += __shfl_xor_sync(0xffffffffu, s0, o);
            s1 += __shfl_xor_sync(0xffffffffu, s1, o);
        }
        if (lane == 0) { ys[0][wid * 8 + jj] = s0; ys[1][wid * 8 + jj] = s1; }
    }
    __syncthreads();

    // epilogue
    if (jg < 2) {
        if (tid < 128) {
            int bb = tid >> 6, jj = tid & 63;
            out[(size_t)t * BB * OUTW + (size_t)(b0 + bb) * OUTW + j0 + jj] =
                ys[bb][jj] + bout[j0 + jj];
        }
    } else if (jg == 6) {
        if (tid < 128) {
            int bb = tid >> 6, jj = tid & 63;
            g_wkey[(b0 + bb) * WWD + jj] = ys[bb][jj] + bkey[4 * 64 + jj];
        }
    } else {
        const int kb = (jg - 2) * 64;   // bkey offset; Kn offset = kb too
        if (tid < 128) {
            int bb = tid >> 6, jj = tid & 63;
            ys[bb][jj] += bkey[kb + jj];
        }
        __syncthreads();
        if (wid < 2) {
            float v0 = ys[wid][lane];
            float v1 = ys[wid][lane + 32];
            float ss = v0 * v0 + v1 * v1;
#pragma unroll
            for (int o = 16; o; o >>= 1) ss += __shfl_xor_sync(0xffffffffu, ss, o);
            if (lane == 0) sinv[wid] = 1.f / (sqrtf(ss) + EPSF);
        }
        __syncthreads();
        if (tid < 128) {
            int bb = tid >> 6, jj = tid & 63;
            g_Kn[(b0 + bb) * (RRD * WWD) + kb + jj] = ys[bb][jj] * sinv[bb];
        }
    }
}

// ==================== K3: sim (shuffle-free) ================================
// grid (16, BB) x 128 threads. Block (nb, b) handles 128 M-rows:
// stage tile into smem (pitch 65 -> conflict-free), each thread privately
// accumulates norm + 4 dots over w (320 FMA, zero shuffles).
__global__ void __launch_bounds__(128) k_sim() {
    __shared__ float tile[128 * 65];                 // 33.3 KB
    __shared__ __align__(16) float s_kn[RRD * WWD];  // 1 KB

    const int b   = blockIdx.y;
    const int nb  = blockIdx.x;      // 16 chunks x 128 rows
    const int tid = threadIdx.x;     // 128

    // stage normalized keys (256 floats)
    s_kn[tid]       = g_Kn[b * RRD * WWD + tid];
    s_kn[tid + 128] = g_Kn[b * RRD * WWD + tid + 128];

    // stage M tile: 128 rows x 64 floats, coalesced float4 loads
    const float4* Mb = (const float4*)(g_M + ((size_t)b * NND + nb * 128) * WWD);
#pragma unroll
    for (int i = 0; i < 16; ++i) {
        int fid = tid + 128 * i;            // 0..2047
        float4 v = Mb[fid];
        int row = fid >> 4, c4 = fid & 15;
        float* dst = tile + row * 65 + c4 * 4;
        dst[0] = v.x; dst[1] = v.y; dst[2] = v.z; dst[3] = v.w;
    }
    __syncthreads();

    // per-thread row reduction
    float ss = 0.f, d0 = 0.f, d1 = 0.f, d2 = 0.f, d3 = 0.f;
    const float* tr = tile + tid * 65;
#pragma unroll
    for (int w4 = 0; w4 < 16; ++w4) {
        float4 k0 = ((const float4*)s_kn)[w4];
        float4 k1 = ((const float4*)s_kn)[16 + w4];
        float4 k2 = ((const float4*)s_kn)[32 + w4];
        float4 k3 = ((const float4*)s_kn)[48 + w4];
        float m0 = tr[w4 * 4 + 0];
        float m1 = tr[w4 * 4 + 1];
        float m2 = tr[w4 * 4 + 2];
        float m3 = tr[w4 * 4 + 3];
        ss += m0 * m0 + m1 * m1 + m2 * m2 + m3 * m3;
        d0 += m0 * k0.x + m1 * k0.y + m2 * k0.z + m3 * k0.w;
        d1 += m0 * k1.x + m1 * k1.y + m2 * k1.z + m3 * k1.w;
        d2 += m0 * k2.x + m1 * k2.y + m2 * k2.z + m3 * k2.w;
        d3 += m0 * k3.x + m1 * k3.y + m2 * k3.z + m3 * k3.w;
    }
    float inv = 1.f / (sqrtf(ss) + EPSF);
    const int n = nb * 128 + tid;
    g_sim[(size_t)(b * RRD + 0) * NND + n] = d0 * inv;
    g_sim[(size_t)(b * RRD + 1) * NND + n] = d1 * inv;
    g_sim[(size_t)(b * RRD + 2) * NND + n] = d2 * inv;
    g_sim[(size_t)(b * RRD + 3) * NND + n] = d3 * inv;
}

// ==================== K4: softmax (+ argmin & read_vec zero on r==0) ========
__global__ void k_softmax(int sel) {
    const int br  = blockIdx.x;       // b*4 + r
    const int tid = threadIdx.x;      // 256
    float* __restrict__ rw_new = g_rw[sel];
    const float* s = g_sim + (size_t)br * NND;
    float v[8];
    float m = -3.4e38f;
#pragma unroll
    for (int j = 0; j < 8; ++j) { v[j] = s[tid + 256 * j]; m = fmaxf(m, v[j]); }
    __shared__ float red[256];
    red[tid] = m; __syncthreads();
    for (int st = 128; st; st >>= 1) { if (tid < st) red[tid] = fmaxf(red[tid], red[tid + st]); __syncthreads(); }
    m = red[0];
    __syncthreads();
    float sum = 0.f;
#pragma unroll
    for (int j = 0; j < 8; ++j) { v[j] = expf(v[j] - m); sum += v[j]; }
    red[tid] = sum; __syncthreads();
    for (int st = 128; st; st >>= 1) { if (tid < st) red[tid] += red[tid + st]; __syncthreads(); }
    float inv = 1.f / red[0];
#pragma unroll
    for (int j = 0; j < 8; ++j)
        rw_new[(size_t)br * NND + tid + 256 * j] = v[j] * inv;

    // r==0 block: argmin(usage[b]) with first-index tie rule + zero read_vec
    if ((br & 3) == 0) {
        const int b = br >> 2;
        __shared__ int si[256];
        __syncthreads();
        float bv = 3.4e38f; int bi = 0;
        for (int i = tid; i < NND; i += 256) {
            float u = g_usage[b * NND + i];
            if (u < bv) { bv = u; bi = i; }
        }
        red[tid] = bv; si[tid] = bi;
        __syncthreads();
        for (int s2 = 128; s2; s2 >>= 1) {
            if (tid < s2) {
                float ov = red[tid + s2]; int oi = si[tid + s2];
                if (ov < red[tid] || (ov == red[tid] && oi < si[tid])) { red[tid] = ov; si[tid] = oi; }
            }
            __syncthreads();
        }
        if (tid == 0) g_lu[b] = si[0];
        g_read_vec[b * RRD * WWD + tid] = 0.f;
    }
}

// ==================== K5: memory update =====================================
// single pass over M: read_vec (old M), write M_new, update usage.
__global__ void __launch_bounds__(256) k_update(int sel,
                                                const float* __restrict__ alpha,
                                                const float* __restrict__ gamma) {
    const int b   = blockIdx.y;
    const int cx  = blockIdx.x;       // 16 chunks x 128 n
    const int tid = threadIdx.x, wid = tid >> 5, lane = tid & 31;
    const float* __restrict__ rw_new = g_rw[sel];
    const float* __restrict__ rw_old = g_rw[sel ^ 1];
    const float sa = 1.f / (1.f + expf(-alpha[0]));
    const float gm = gamma[0];
    const int lu = g_lu[b];

    __shared__ __align__(16) float wk[WWD];
    if (tid < WWD) wk[tid] = g_wkey[b * WWD + tid];
    __syncthreads();
    const float2 wk2 = ((const float2*)wk)[lane];

    float2 a0 = {0.f, 0.f}, a1 = {0.f, 0.f}, a2 = {0.f, 0.f}, a3 = {0.f, 0.f};
#pragma unroll 4
    for (int i = 0; i < 16; ++i) {
        int n = cx * 128 + wid * 16 + i;
        size_t moff = (size_t)(b * NND + n) * WWD;
        float2 m = ((const float2*)(g_M + moff))[lane];
        float r0o = rw_old[(size_t)(b * RRD + 0) * NND + n];
        float r1o = rw_old[(size_t)(b * RRD + 1) * NND + n];
        float r2o = rw_old[(size_t)(b * RRD + 2) * NND + n];
        float r3o = rw_old[(size_t)(b * RRD + 3) * NND + n];
        float r0 = rw_new[(size_t)(b * RRD + 0) * NND + n];
        float r1 = rw_new[(size_t)(b * RRD + 1) * NND + n];
        float r2 = rw_new[(size_t)(b * RRD + 2) * NND + n];
        float r3 = rw_new[(size_t)(b * RRD + 3) * NND + n];
        float so = r0o + r1o + r2o + r3o;
        bool is_lu = (n == lu);
        float ww = sa * so + (is_lu ? (1.f - sa) : 0.f);
        float2 mn;
        mn.x = (is_lu ? 0.f : m.x) + ww * wk2.x;
        mn.y = (is_lu ? 0.f : m.y) + ww * wk2.y;
        ((float2*)(g_M + moff))[lane] = mn;
        // read_vec uses OLD M
        a0.x += r0 * m.x; a0.y += r0 * m.y;
        a1.x += r1 * m.x; a1.y += r1 * m.y;
        a2.x += r2 * m.x; a2.y += r2 * m.y;
        a3.x += r3 * m.x; a3.y += r3 * m.y;
        if (lane == 0)
            g_usage[b * NND + n] = gm * g_usage[b * NND + n] + (r0 + r1 + r2 + r3) + ww;
    }
    // cross-warp reduce into read_vec
    __shared__ float red[8][RRD * WWD];
    float* rp = red[wid];
    rp[0 * WWD + 2 * lane] = a0.x; rp[0 * WWD + 2 * lane + 1] = a0.y;
    rp[1 * WWD + 2 * lane] = a1.x; rp[1 * WWD + 2 * lane + 1] = a1.y;
    rp[2 * WWD + 2 * lane] = a2.x; rp[2 * WWD + 2 * lane + 1] = a2.y;
    rp[3 * WWD + 2 * lane] = a3.x; rp[3 * WWD + 2 * lane + 1] = a3.y;
    __syncthreads();
    if (tid < RRD * WWD) {
        float s = 0.f;
#pragma unroll
        for (int w = 0; w < 8; ++w) s += red[w][tid];
        atomicAdd(&g_read_vec[b * RRD * WWD + tid], s);
    }
}

// ------------------------------- launcher ------------------------------------
extern "C" void kernel_launch(void* const* d_in, const int* in_sizes, int n_in,
                              void* d_out, int out_size) {
    const float* x_seq = (const float*)d_in[0];
    const float* Wih   = (const float*)d_in[1];
    const float* Whh   = (const float*)d_in[2];
    const float* bih   = (const float*)d_in[3];
    const float* bhh   = (const float*)d_in[4];
    const float* Wout  = (const float*)d_in[5];
    const float* bout  = (const float*)d_in[6];
    const float* Wkey  = (const float*)d_in[7];
    const float* bkey  = (const float*)d_in[8];
    const float* alpha = (const float*)d_in[9];
    const float* gamma = (const float*)d_in[10];
    float* out = (float*)d_out;

    k_reset<<<32768, 256>>>();

    for (int t = 0; t < TT; ++t) {
        const int sel = t & 1;
        k_gates<<<JGATE / 16, 256>>>(x_seq + (size_t)t * BB * INW,
                                     Wih, Whh, bih, bhh, sel);
        k_ok2<<<dim3(7, 32), 256>>>(Wout, Wkey, bout, bkey, out, t, sel);
        k_sim<<<dim3(16, BB), 128>>>();
        k_softmax<<<BB * RRD, 256>>>(sel);
        k_update<<<dim3(16, BB), 256>>>(sel, alpha, gamma);
    }
}

// round 9
// speedup vs baseline: 2.3096x; 1.0467x over previous
#include <cuda_runtime.h>
#include <math.h>
#include <stdint.h>

// Problem constants
#define BB    64
#define TT    128
#define INW   128
#define HHD   512
#define NND   2048
#define WWD   64
#define OUTW  128
#define RRD   4
#define CTRL  384            // IN + R*W
#define KGATE 896            // CTRL + H  (14 tiles of 64)
#define JGATE 2048           // 4*H
#define JOK   448            // OUT + (R+1)*W
#define EPSF  1e-8f

// ------------------------- persistent device state -------------------------
__device__ float g_h[2][BB * HHD];             // ping-pong hidden state
__device__ float g_c[BB * HHD];
__device__ float g_M[BB * NND * WWD];          // 33.5 MB
__device__ float g_usage[BB * NND];
__device__ float g_rw[2][BB * RRD * NND];      // ping-pong read weights
__device__ float g_read_vec[BB * RRD * WWD];
__device__ float g_sim[BB * RRD * NND];        // raw cosine sims
__device__ float2 g_stats[BB * RRD * 16];      // per-chunk (max, sumexp)
__device__ float g_Kn[BB * RRD * WWD];         // normalized read keys
__device__ float g_wkey[BB * WWD];             // write key
__device__ int   g_lu[BB];                     // argmin(usage) per batch

// ------------------------------- reset -------------------------------------
__global__ void k_reset() {
    long idx = (long)blockIdx.x * blockDim.x + threadIdx.x;
    if (idx < (long)BB * NND * WWD) g_M[idx] = 1e-6f;
    if (idx < BB * HHD) { g_h[0][idx] = 0.f; g_h[1][idx] = 0.f; g_c[idx] = 0.f; }
    if (idx < BB * NND) g_usage[idx] = 0.f;
    if (idx < BB * RRD * NND) { g_rw[0][idx] = 0.f; g_rw[1][idx] = 0.f; }
    if (idx < BB * RRD * WWD) g_read_vec[idx] = 0.f;
    if (idx < BB) g_lu[idx] = 0;
}

__device__ __forceinline__ float sigm(float x) { return 1.f / (1.f + expf(-x)); }

// ==================== K1: gates GEMM + LSTM epilogue ========================
// grid 128 blocks x 256 threads. Block bid owns hh0 = bid*4: the 4 hidden
// units hh0..hh0+3 across ALL 4 gates (16 j values), all 64 batches, full K.
// Register double-buffering: tile t+1 loads overlap tile t compute.
__global__ void __launch_bounds__(256) k_gates(
    const float* __restrict__ xt,
    const float* __restrict__ Wih, const float* __restrict__ Whh,
    const float* __restrict__ bih, const float* __restrict__ bhh,
    int sel)
{
    __shared__ __align__(16) float4 xs4[BB * 16];   // 64 b x 64 k = 16 KB
    __shared__ __align__(16) float4 ws4[16 * 17];   // 16 j x 64 k padded
    __shared__ float sacc[16][BB];                  // acc staging, 4 KB

    const int tid = threadIdx.x;
    const int hq  = tid & 15;       // jj
    const int bq  = tid >> 4;       // 16 batch quads
    const int hh0 = blockIdx.x * 4;
    const float* __restrict__ hr = g_h[sel];

    const int xb   = tid >> 4;
    const int xk4  = tid & 15;
    const int wr_r = tid >> 4;
    const int jr   = hh0 + (wr_r & 3) + (wr_r >> 2) * 512;

    float acc[4] = {0.f, 0.f, 0.f, 0.f};

    float4 xreg[4];
    float4 wreg;

    // prologue: load tile 0 into registers
    {
        const int k0 = 0;
#pragma unroll
        for (int li = 0; li < 4; ++li) {
            int b = xb + 16 * li;
            int k = k0 + xk4 * 4;
            const float* src;
            if (k < INW)       src = xt + b * INW + k;
            else if (k < CTRL) src = g_read_vec + b * (RRD * WWD) + (k - INW);
            else               src = hr + b * HHD + (k - CTRL);
            xreg[li] = *reinterpret_cast<const float4*>(src);
        }
        int k = k0 + xk4 * 4;
        const float* src = (k < CTRL) ? (Wih + (size_t)jr * CTRL + k)
                                      : (Whh + (size_t)jr * HHD + (k - CTRL));
        wreg = *reinterpret_cast<const float4*>(src);
    }

    for (int tl = 0; tl < 14; ++tl) {
#pragma unroll
        for (int li = 0; li < 4; ++li)
            xs4[(xb + 16 * li) * 16 + xk4] = xreg[li];
        ws4[wr_r * 17 + xk4] = wreg;
        __syncthreads();

        if (tl + 1 < 14) {
            const int k0 = (tl + 1) * 64;
#pragma unroll
            for (int li = 0; li < 4; ++li) {
                int b = xb + 16 * li;
                int k = k0 + xk4 * 4;
                const float* src;
                if (k < INW)       src = xt + b * INW + k;
                else if (k < CTRL) src = g_read_vec + b * (RRD * WWD) + (k - INW);
                else               src = hr + b * HHD + (k - CTRL);
                xreg[li] = *reinterpret_cast<const float4*>(src);
            }
            int k = k0 + xk4 * 4;
            const float* src = (k < CTRL) ? (Wih + (size_t)jr * CTRL + k)
                                          : (Whh + (size_t)jr * HHD + (k - CTRL));
            wreg = *reinterpret_cast<const float4*>(src);
        }

#pragma unroll
        for (int kk = 0; kk < 16; ++kk) {
            float4 wv = ws4[hq * 17 + kk];
#pragma unroll
            for (int i = 0; i < 4; ++i) {
                float4 xv = xs4[(bq * 4 + i) * 16 + kk];
                acc[i] += xv.x * wv.x + xv.y * wv.y + xv.z * wv.z + xv.w * wv.w;
            }
        }
        __syncthreads();
    }

#pragma unroll
    for (int i = 0; i < 4; ++i) sacc[hq][bq * 4 + i] = acc[i];
    __syncthreads();

    {
        const int b  = tid & 63;
        const int dd = tid >> 6;
        const int hh = hh0 + dd;
        float gi = sacc[0 * 4 + dd][b] + bih[hh]           + bhh[hh];
        float gf = sacc[1 * 4 + dd][b] + bih[512 + hh]     + bhh[512 + hh];
        float gg = sacc[2 * 4 + dd][b] + bih[1024 + hh]    + bhh[1024 + hh];
        float go = sacc[3 * 4 + dd][b] + bih[1536 + hh]    + bhh[1536 + hh];
        float c  = g_c[b * HHD + hh];
        float cn = sigm(gf) * c + sigm(gi) * tanhf(gg);
        float hn = sigm(go) * tanhf(cn);
        g_c[b * HHD + hh] = cn;
        g_h[sel ^ 1][b * HHD + hh] = hn;
    }
}

// ========== K2: out+keys GEMM with fused finish epilogue + argmin ===========
// grid (8 j-groups, 32 batch-pairs) x 256 threads.
//   jg 0,1  -> out rows (bias bout)
//   jg 2..5 -> read key r=jg-2: add bkey, L2-normalize, write g_Kn
//   jg 6    -> write key: add bkey, write g_wkey
//   jg 7    -> argmin(usage) for the 2 batches (usage is from prev step,
//              final at step start) + zero read_vec for K5's accumulation.
__global__ void __launch_bounds__(256) k_ok2(
    const float* __restrict__ Wout, const float* __restrict__ Wkey,
    const float* __restrict__ bout, const float* __restrict__ bkey,
    float* __restrict__ out, int t, int sel)
{
    __shared__ __align__(16) float4 hs[2][128];   // 2 batches x 512 floats
    __shared__ float ys[2][64];
    __shared__ float sinv[2];
    __shared__ float asv[256];
    __shared__ int   asi[256];

    const int tid  = threadIdx.x;
    const int wid  = tid >> 5, lane = tid & 31;
    const int jg   = blockIdx.x;
    const int b0   = blockIdx.y * 2;

    if (jg == 7) {
        // argmin over usage for batches b0, b0+1 (128 threads each)
        const int half = tid >> 7;
        const int ht   = tid & 127;
        const int b    = b0 + half;
        float bv = 3.4e38f; int bi = 0;
        for (int i = ht; i < NND; i += 128) {
            float u = g_usage[b * NND + i];
            if (u < bv) { bv = u; bi = i; }
        }
        asv[tid] = bv; asi[tid] = bi;
        __syncthreads();
        for (int s = 64; s; s >>= 1) {
            if (ht < s) {
                float ov = asv[tid + s]; int oi = asi[tid + s];
                if (ov < asv[tid] || (ov == asv[tid] && oi < asi[tid])) {
                    asv[tid] = ov; asi[tid] = oi;
                }
            }
            __syncthreads();
        }
        if (ht == 0) g_lu[b] = asi[tid];
        // zero read_vec (256 floats per batch, 128 threads -> 2 each)
        g_read_vec[b * RRD * WWD + ht]       = 0.f;
        g_read_vec[b * RRD * WWD + ht + 128] = 0.f;
        return;
    }

    const int j0 = jg * 64;
    const float* __restrict__ hn = g_h[sel ^ 1];

    {
        int bb = tid >> 7, idx = tid & 127;
        hs[bb][idx] = ((const float4*)(hn + (size_t)(b0 + bb) * HHD))[idx];
    }
    __syncthreads();

#pragma unroll 2
    for (int jj = 0; jj < 8; ++jj) {
        int j = j0 + wid * 8 + jj;
        const float* wrow = (j < OUTW) ? (Wout + (size_t)j * HHD)
                                       : (Wkey + (size_t)(j - OUTW) * HHD);
        const float4* w4 = (const float4*)wrow;
        float s0 = 0.f, s1 = 0.f;
#pragma unroll
        for (int it = 0; it < 4; ++it) {
            float4 w = w4[lane + 32 * it];
            float4 h0 = hs[0][lane + 32 * it];
            float4 h1 = hs[1][lane + 32 * it];
            s0 += w.x * h0.x + w.y * h0.y + w.z * h0.z + w.w * h0.w;
            s1 += w.x * h1.x + w.y * h1.y + w.z * h1.z + w.w * h1.w;
        }
#pragma unroll
        for (int o = 16; o; o >>= 1) {
            s0 += __shfl_xor_sync(0xffffffffu, s0, o);
            s1 += __shfl_xor_sync(0xffffffffu, s1, o);
        }
        if (lane == 0) { ys[0][wid * 8 + jj] = s0; ys[1][wid * 8 + jj] = s1; }
    }
    __syncthreads();

    if (jg < 2) {
        if (tid < 128) {
            int bb = tid >> 6, jj = tid & 63;
            out[(size_t)t * BB * OUTW + (size_t)(b0 + bb) * OUTW + j0 + jj] =
                ys[bb][jj] + bout[j0 + jj];
        }
    } else if (jg == 6) {
        if (tid < 128) {
            int bb = tid >> 6, jj = tid & 63;
            g_wkey[(b0 + bb) * WWD + jj] = ys[bb][jj] + bkey[4 * 64 + jj];
        }
    } else {
        const int kb = (jg - 2) * 64;
        if (tid < 128) {
            int bb = tid >> 6, jj = tid & 63;
            ys[bb][jj] += bkey[kb + jj];
        }
        __syncthreads();
        if (wid < 2) {
            float v0 = ys[wid][lane];
            float v1 = ys[wid][lane + 32];
            float ss = v0 * v0 + v1 * v1;
#pragma unroll
            for (int o = 16; o; o >>= 1) ss += __shfl_xor_sync(0xffffffffu, ss, o);
            if (lane == 0) sinv[wid] = 1.f / (sqrtf(ss) + EPSF);
        }
        __syncthreads();
        if (tid < 128) {
            int bb = tid >> 6, jj = tid & 63;
            g_Kn[(b0 + bb) * (RRD * WWD) + kb + jj] = ys[bb][jj] * sinv[bb];
        }
    }
}

// ==================== K3: sim + online softmax stats ========================
// grid (16, BB) x 128 threads, 8 blocks/SM. Two w-phases of 32 (tile 17 KB).
// Each thread privately reduces one M-row (zero shuffles in the main path),
// then one warp per r computes the chunk's (max, sumexp) -> g_stats.
__global__ void __launch_bounds__(128, 8) k_sim() {
    __shared__ float tile[128 * 33];                 // 16.9 KB
    __shared__ __align__(16) float s_kn[RRD * WWD];  // 1 KB
    __shared__ float s_sv[4][128];                   // 2 KB

    const int b    = blockIdx.y;
    const int nb   = blockIdx.x;     // 16 chunks x 128 rows
    const int tid  = threadIdx.x;    // 128
    const int wid  = tid >> 5, lane = tid & 31;

    s_kn[tid]       = g_Kn[b * RRD * WWD + tid];
    s_kn[tid + 128] = g_Kn[b * RRD * WWD + tid + 128];

    const float4* Mb = (const float4*)(g_M + ((size_t)b * NND + nb * 128) * WWD);

    float ss = 0.f, d0 = 0.f, d1 = 0.f, d2 = 0.f, d3 = 0.f;

#pragma unroll
    for (int p = 0; p < 2; ++p) {
        __syncthreads();
        // stage half tile: 128 rows x 32 floats (8 float4 per thread, coalesced)
#pragma unroll
        for (int i = 0; i < 8; ++i) {
            int fid = tid + 128 * i;
            int row = fid >> 3, c4 = fid & 7;
            float4 v = Mb[row * 16 + p * 8 + c4];
            float* dst = tile + row * 33 + c4 * 4;
            dst[0] = v.x; dst[1] = v.y; dst[2] = v.z; dst[3] = v.w;
        }
        __syncthreads();
        const float* tr = tile + tid * 33;
        const float4* kk0 = (const float4*)(s_kn + 0 * 64 + p * 32);
        const float4* kk1 = (const float4*)(s_kn + 1 * 64 + p * 32);
        const float4* kk2 = (const float4*)(s_kn + 2 * 64 + p * 32);
        const float4* kk3 = (const float4*)(s_kn + 3 * 64 + p * 32);
#pragma unroll
        for (int w4 = 0; w4 < 8; ++w4) {
            float m0 = tr[w4 * 4 + 0];
            float m1 = tr[w4 * 4 + 1];
            float m2 = tr[w4 * 4 + 2];
            float m3 = tr[w4 * 4 + 3];
            float4 a = kk0[w4], bb = kk1[w4], c = kk2[w4], d = kk3[w4];
            ss += m0 * m0 + m1 * m1 + m2 * m2 + m3 * m3;
            d0 += m0 * a.x + m1 * a.y + m2 * a.z + m3 * a.w;
            d1 += m0 * bb.x + m1 * bb.y + m2 * bb.z + m3 * bb.w;
            d2 += m0 * c.x + m1 * c.y + m2 * c.z + m3 * c.w;
            d3 += m0 * d.x + m1 * d.y + m2 * d.z + m3 * d.w;
        }
    }

    float inv = 1.f / (sqrtf(ss) + EPSF);
    float s0 = d0 * inv, s1 = d1 * inv, s2 = d2 * inv, s3 = d3 * inv;
    const int n = nb * 128 + tid;
    g_sim[(size_t)(b * RRD + 0) * NND + n] = s0;
    g_sim[(size_t)(b * RRD + 1) * NND + n] = s1;
    g_sim[(size_t)(b * RRD + 2) * NND + n] = s2;
    g_sim[(size_t)(b * RRD + 3) * NND + n] = s3;
    s_sv[0][tid] = s0; s_sv[1][tid] = s1; s_sv[2][tid] = s2; s_sv[3][tid] = s3;
    __syncthreads();

    // warp wid: chunk stats for r = wid
    {
        float v0 = s_sv[wid][lane];
        float v1 = s_sv[wid][lane + 32];
        float v2 = s_sv[wid][lane + 64];
        float v3 = s_sv[wid][lane + 96];
        float m = fmaxf(fmaxf(v0, v1), fmaxf(v2, v3));
#pragma unroll
        for (int o = 16; o; o >>= 1) m = fmaxf(m, __shfl_xor_sync(0xffffffffu, m, o));
        float S = expf(v0 - m) + expf(v1 - m) + expf(v2 - m) + expf(v3 - m);
#pragma unroll
        for (int o = 16; o; o >>= 1) S += __shfl_xor_sync(0xffffffffu, S, o);
        if (lane == 0)
            g_stats[(b * RRD + wid) * 16 + nb] = make_float2(m, S);
    }
}

// ==================== K4: memory update (softmax fused in) ==================
// grid (16, BB) x 256. Prologue: combine the 16 chunk stats per r, compute
// rw_new = exp(sim - m)/S for this block's 128 rows into smem (also written
// to g_rw[sel] for next step's rw_old). Main pass over M unchanged.
__global__ void __launch_bounds__(256) k_update(int sel,
                                                const float* __restrict__ alpha,
                                                const float* __restrict__ gamma) {
    const int b   = blockIdx.y;
    const int cx  = blockIdx.x;       // 16 chunks x 128 n
    const int tid = threadIdx.x, wid = tid >> 5, lane = tid & 31;
    const float* __restrict__ rw_old = g_rw[sel ^ 1];
    float* __restrict__ rw_out = g_rw[sel];
    const float sa = 1.f / (1.f + expf(-alpha[0]));
    const float gm = gamma[0];
    const int lu = g_lu[b];

    __shared__ __align__(16) float wk[WWD];
    __shared__ float2 s_st[64];
    __shared__ float s_m[4], s_is[4];
    __shared__ float srw[4][128];

    if (tid < 64) s_st[tid] = g_stats[(b * RRD + (tid >> 4)) * 16 + (tid & 15)];
    else if (tid < 128) wk[tid - 64] = g_wkey[b * WWD + (tid - 64)];
    __syncthreads();
    if (tid < 4) {
        float m = -3.4e38f;
#pragma unroll
        for (int i = 0; i < 16; ++i) m = fmaxf(m, s_st[tid * 16 + i].x);
        float S = 0.f;
#pragma unroll
        for (int i = 0; i < 16; ++i) {
            float2 p = s_st[tid * 16 + i];
            S += p.y * expf(p.x - m);
        }
        s_m[tid] = m; s_is[tid] = 1.f / S;
    }
    __syncthreads();

    const int n0 = cx * 128;
#pragma unroll
    for (int k2 = 0; k2 < 2; ++k2) {
        int idx = tid + 256 * k2;
        int r = idx >> 7, nl = idx & 127;
        float sv = g_sim[(size_t)(b * RRD + r) * NND + n0 + nl];
        float e = expf(sv - s_m[r]) * s_is[r];
        srw[r][nl] = e;
        rw_out[(size_t)(b * RRD + r) * NND + n0 + nl] = e;
    }
    __syncthreads();

    const float2 wk2 = ((const float2*)wk)[lane];

    float2 a0 = {0.f, 0.f}, a1 = {0.f, 0.f}, a2 = {0.f, 0.f}, a3 = {0.f, 0.f};
#pragma unroll 4
    for (int i = 0; i < 16; ++i) {
        int nl = wid * 16 + i;
        int n  = n0 + nl;
        size_t moff = (size_t)(b * NND + n) * WWD;
        float2 m = ((const float2*)(g_M + moff))[lane];
        float r0o = rw_old[(size_t)(b * RRD + 0) * NND + n];
        float r1o = rw_old[(size_t)(b * RRD + 1) * NND + n];
        float r2o = rw_old[(size_t)(b * RRD + 2) * NND + n];
        float r3o = rw_old[(size_t)(b * RRD + 3) * NND + n];
        float r0 = srw[0][nl];
        float r1 = srw[1][nl];
        float r2 = srw[2][nl];
        float r3 = srw[3][nl];
        float so = r0o + r1o + r2o + r3o;
        bool is_lu = (n == lu);
        float ww = sa * so + (is_lu ? (1.f - sa) : 0.f);
        float2 mn;
        mn.x = (is_lu ? 0.f : m.x) + ww * wk2.x;
        mn.y = (is_lu ? 0.f : m.y) + ww * wk2.y;
        ((float2*)(g_M + moff))[lane] = mn;
        // read_vec uses OLD M
        a0.x += r0 * m.x; a0.y += r0 * m.y;
        a1.x += r1 * m.x; a1.y += r1 * m.y;
        a2.x += r2 * m.x; a2.y += r2 * m.y;
        a3.x += r3 * m.x; a3.y += r3 * m.y;
        if (lane == 0)
            g_usage[b * NND + n] = gm * g_usage[b * NND + n] + (r0 + r1 + r2 + r3) + ww;
    }
    // cross-warp reduce into read_vec
    __shared__ float red[8][RRD * WWD];
    float* rp = red[wid];
    rp[0 * WWD + 2 * lane] = a0.x; rp[0 * WWD + 2 * lane + 1] = a0.y;
    rp[1 * WWD + 2 * lane] = a1.x; rp[1 * WWD + 2 * lane + 1] = a1.y;
    rp[2 * WWD + 2 * lane] = a2.x; rp[2 * WWD + 2 * lane + 1] = a2.y;
    rp[3 * WWD + 2 * lane] = a3.x; rp[3 * WWD + 2 * lane + 1] = a3.y;
    __syncthreads();
    if (tid < RRD * WWD) {
        float s = 0.f;
#pragma unroll
        for (int w = 0; w < 8; ++w) s += red[w][tid];
        atomicAdd(&g_read_vec[b * RRD * WWD + tid], s);
    }
}

// ------------------------------- launcher ------------------------------------
extern "C" void kernel_launch(void* const* d_in, const int* in_sizes, int n_in,
                              void* d_out, int out_size) {
    const float* x_seq = (const float*)d_in[0];
    const float* Wih   = (const float*)d_in[1];
    const float* Whh   = (const float*)d_in[2];
    const float* bih   = (const float*)d_in[3];
    const float* bhh   = (const float*)d_in[4];
    const float* Wout  = (const float*)d_in[5];
    const float* bout  = (const float*)d_in[6];
    const float* Wkey  = (const float*)d_in[7];
    const float* bkey  = (const float*)d_in[8];
    const float* alpha = (const float*)d_in[9];
    const float* gamma = (const float*)d_in[10];
    float* out = (float*)d_out;

    k_reset<<<32768, 256>>>();

    for (int t = 0; t < TT; ++t) {
        const int sel = t & 1;
        k_gates<<<JGATE / 16, 256>>>(x_seq + (size_t)t * BB * INW,
                                     Wih, Whh, bih, bhh, sel);
        k_ok2<<<dim3(8, 32), 256>>>(Wout, Wkey, bout, bkey, out, t, sel);
        k_sim<<<dim3(16, BB), 128>>>();
        k_update<<<dim3(16, BB), 256>>>(sel, alpha, gamma);
    }
}